// round 15
// baseline (speedup 1.0000x reference)
#include <cuda_runtime.h>

#define NROWS  512
#define DDIM   512
#define TILE   64
#define NT     8            // 512/64 tile-rows
#define NTILES 36           // upper triangle of 8x8
#define KSPLIT 8
#define KLEN   64           // 512/KSPLIT
#define GRID   (NTILES * KSPLIT)   // 288 blocks; 2/SM co-resident (288 < 296)

// Scratch (allocation-free rule: __device__ globals)
__device__ float g_part[KSPLIT * NROWS * NROWS];  // k-split partial dots (8 MB)
__device__ float g_diag[KSPLIT][NROWS];           // k-split partial diagonal
__device__ int   g_bar  = 0;                      // phase barrier (reset each call)
__device__ int   g_done = 0;                      // completion counter (reset each call)

// ---------------------------------------------------------------------------
// Fused kernel: GEMM (phase 1) + device-wide spin barrier + triplet (phase 2).
// 288 blocks x 256 threads, __launch_bounds__(256,2) -> 2 blocks/SM resident,
// so (a) the spin barrier is deadlock-free, (b) two blocks interleave to hide
// each other's load/sync stalls.
//
// Phase 1: 64x64 upper-triangle tiles (36) x 8-way k-split, 4x4 register
// micro-tile, XOR-swizzled staging, SOFTWARE-PIPELINED global prefetch
// (chunk k+1 loads issue before chunk k's compute -> latency hidden).
//
// Phase 2: 512 anchor-slots over 288 blocks (slot = bid + 288*w, w<2;
// anchor = slot*293 & 511). Batched 8-partial sums, uniform ballot
// compaction, np x 16 register fmax hot loop, one atomicAdd per block.
// ---------------------------------------------------------------------------
__global__ void __launch_bounds__(256, 2)
fused_kernel(const float* __restrict__ embs,
             const void* __restrict__ idxraw,
             float* __restrict__ out) {
    const int tid = threadIdx.x;          // 0..255
    const int bid = blockIdx.x;

    __shared__ float4 Ash4[32 * 16];      // 8 KB (phase 1: A stage; phase 2: tables)
    __shared__ float4 Bsh4[32 * 16];      // 8 KB

    // ======================= Phase 1: GEMM =======================
    {
        if (bid == 0 && tid == 0) *out = 0.0f;   // published by the barrier fence

        const int tile = bid >> 3;        // 0..35
        const int s    = bid & 7;         // k-slice
        int rem = tile, bm = 0;
        while (rem >= NT - bm) { rem -= NT - bm; bm++; }
        const int bn = bm + rem;
        const int k0 = s * KLEN;

        // Staging roles: 128 threads per operand (A: tid<128, B: tid>=128).
        const int tsel = tid >> 7;
        const int tid7 = tid & 127;
        const int kb   = tid7 & 7;        // k-quad (coalesced gmem dim)
        const int rb   = tid7 >> 3;       // row-quad
        const int baserow = (tsel ? bn : bm) * TILE + 4 * rb;
        const float* __restrict__ gsrc = embs + baserow * DDIM + k0 + 4 * kb;
        float4* const dst = tsel ? Bsh4 : Ash4;

        const int tx = tid & 15;
        const int ty = tid >> 4;

        float acc[4][4];
#pragma unroll
        for (int i = 0; i < 4; i++)
#pragma unroll
            for (int j = 0; j < 4; j++) acc[i][j] = 0.f;

        // Prefetch chunk 0
        float4 v0 = *(const float4*)(gsrc);
        float4 v1 = *(const float4*)(gsrc + DDIM);
        float4 v2 = *(const float4*)(gsrc + 2 * DDIM);
        float4 v3 = *(const float4*)(gsrc + 3 * DDIM);

#pragma unroll
        for (int kk = 0; kk < KLEN; kk += 32) {
            __syncthreads();              // previous chunk fully consumed
            const int q = rb ^ kb;        // swizzle: conflict-free stores+reads
            dst[(4 * kb + 0) * 16 + q] = make_float4(v0.x, v1.x, v2.x, v3.x);
            dst[(4 * kb + 1) * 16 + q] = make_float4(v0.y, v1.y, v2.y, v3.y);
            dst[(4 * kb + 2) * 16 + q] = make_float4(v0.z, v1.z, v2.z, v3.z);
            dst[(4 * kb + 3) * 16 + q] = make_float4(v0.w, v1.w, v2.w, v3.w);
            __syncthreads();

            // Software pipeline: issue next chunk's loads BEFORE compute
            if (kk + 32 < KLEN) {
                v0 = *(const float4*)(gsrc + kk + 32);
                v1 = *(const float4*)(gsrc + DDIM + kk + 32);
                v2 = *(const float4*)(gsrc + 2 * DDIM + kk + 32);
                v3 = *(const float4*)(gsrc + 3 * DDIM + kk + 32);
            }

#pragma unroll
            for (int k = 0; k < 32; k++) {
                const int sw = (k >> 2) & 7;
                float4 a = Ash4[k * 16 + (ty ^ sw)];
                float4 b = Bsh4[k * 16 + (tx ^ sw)];
                acc[0][0] += a.x * b.x; acc[0][1] += a.x * b.y;
                acc[0][2] += a.x * b.z; acc[0][3] += a.x * b.w;
                acc[1][0] += a.y * b.x; acc[1][1] += a.y * b.y;
                acc[1][2] += a.y * b.z; acc[1][3] += a.y * b.w;
                acc[2][0] += a.z * b.x; acc[2][1] += a.z * b.y;
                acc[2][2] += a.z * b.z; acc[2][3] += a.z * b.w;
                acc[3][0] += a.w * b.x; acc[3][1] += a.w * b.y;
                acc[3][2] += a.w * b.z; acc[3][3] += a.w * b.w;
            }
        }

        float* __restrict__ outp = g_part + s * (NROWS * NROWS);
        const int row0 = bm * TILE + 4 * ty;
        const int col0 = bn * TILE + 4 * tx;
#pragma unroll
        for (int i = 0; i < 4; i++)
            *(float4*)&outp[(row0 + i) * NROWS + col0] =
                make_float4(acc[i][0], acc[i][1], acc[i][2], acc[i][3]);

        if (bm == bn && tx == ty) {
#pragma unroll
            for (int d = 0; d < 4; d++) g_diag[s][row0 + d] = acc[d][d];
        }
    }

    // =================== Device-wide barrier ===================
    __syncthreads();
    __threadfence();                      // publish g_part / g_diag / *out
    if (tid == 0) {
        atomicAdd(&g_bar, 1);
        while (*(volatile int*)&g_bar < GRID) { }
    }
    __syncthreads();
    __threadfence();                      // acquire other blocks' writes

    // ======================= Phase 2: triplet =======================
    {
        const int w    = tid >> 5;        // warp 0..7
        const int lane = tid & 31;

        // Overlay tables onto the dead GEMM staging smem (Ash4 = 8 KB).
        float* const s_inv = (float*)Ash4;            // 512 floats (2 KB)
        int*   const s_cls = (int*)(s_inv + NROWS);   // 512 ints   (2 KB)
        float* const s_pos = (float*)(s_cls + NROWS); // 8 warps x 32 (1 KB)
        __shared__ float s_wsum[8];
        __shared__ int   fl;

        // Dtype probe (per-block): odd int32 positions within the first
        // 2048 bytes. int64 layout -> all zero high words; int32 -> ids.
        if (tid == 0) fl = 0;
        __syncthreads();
        if (((const int*)idxraw)[2 * tid + 1] != 0) atomicOr(&fl, 1);
        __syncthreads();
        const int is32 = fl;
        const int* __restrict__ i32 = (const int*)idxraw;
        const long long* __restrict__ i64 = (const long long*)idxraw;

#pragma unroll
        for (int e = 0; e < 2; e++) {
            int r = tid + e * 256;
            float d = 0.f;
#pragma unroll
            for (int p = 0; p < KSPLIT; p++) d += g_diag[p][r];   // coalesced
            s_inv[r] = 1.0f / fmaxf(sqrtf(d), 1e-8f);
            s_cls[r] = is32 ? i32[r] : (int)i64[r];
        }
        __syncthreads();

        float wsum = 0.f;
        const int slot = bid + GRID * w;  // warps 0..1 carry slots (576 >= 512)
        if (w < 2 && slot < 512) {
            const int i = (slot * 293) & 511;   // odd multiplier: bijection, balances load
            const int   ci   = s_cls[i];
            const float invi = s_inv[i];
            const int   rowbase = i * NROWS;

            // Phase A: batched partial-sum loads; no warp collectives here.
            float c[16];
#pragma unroll
            for (int sl = 0; sl < 16; sl++) {
                int j = i + 1 + lane + sl * 32;
                float sum = 0.f;
                if (j < NROWS) {
#pragma unroll
                    for (int p = 0; p < KSPLIT; p++)
                        sum += g_part[p * (NROWS * NROWS) + rowbase + j];
                    sum *= invi * s_inv[j];
                }
                c[sl] = sum;
            }

            // Phase B: uniform ballot compaction (all lanes hit every ballot).
            int np = 0;
#pragma unroll
            for (int sl = 0; sl < 16; sl++) {
                int j = i + 1 + lane + sl * 32;
                bool valid = (j < NROWS);
                bool match = valid && (s_cls[j] == ci);
                unsigned mask = __ballot_sync(0xffffffffu, match);
                if (match) {
                    int off = np + __popc(mask & ((1u << lane) - 1u));
                    if (off < 32) s_pos[w * 32 + off] = c[sl];
                }
                np += __popc(mask);
                c[sl] = (valid && !match) ? (c[sl] + 1.0f) : -1e30f;  // sentinel
            }
            if (np > 32) np = 32;         // capacity guard (expected np ~ 4)
            __syncwarp();

            // Hot loop: np broadcast-LDS reads, 16 unrolled register fmax each.
            float s0 = 0.f, s1 = 0.f;
            for (int p = 0; p < np; p++) {
                float bp = s_pos[w * 32 + p];
#pragma unroll
                for (int sl = 0; sl < 16; sl += 2) {
                    s0 += fmaxf(c[sl]     - bp, 0.0f);
                    s1 += fmaxf(c[sl + 1] - bp, 0.0f);
                }
            }
            wsum = s0 + s1;
        }

#pragma unroll
        for (int o = 16; o; o >>= 1) wsum += __shfl_xor_sync(0xffffffffu, wsum, o);
        if (lane == 0) s_wsum[w] = wsum;
        __syncthreads();
        if (tid < 8) {
            float v = s_wsum[tid];
#pragma unroll
            for (int o = 4; o; o >>= 1) v += __shfl_xor_sync(0xffu, v, o);
            if (tid == 0) atomicAdd(out, v);   // one atomic per block
        }
    }

    // ============ Reset counters for next graph replay ============
    // Every block increments g_done only after exiting the spin, so the
    // last finisher can safely zero both counters.
    __syncthreads();
    if (tid == 0) {
        int d = atomicAdd(&g_done, 1);
        if (d == GRID - 1) {
            g_bar  = 0;
            g_done = 0;
            __threadfence();
        }
    }
}

extern "C" void kernel_launch(void* const* d_in, const int* in_sizes, int n_in,
                              void* d_out, int out_size) {
    const float* embs = (const float*)d_in[0];
    const void*  indices = d_in[1];
    float* out = (float*)d_out;

    fused_kernel<<<GRID, 256>>>(embs, indices, out);
}